// round 6
// baseline (speedup 1.0000x reference)
#include <cuda_runtime.h>

#define NN 50000
#define EE 800000
#define SCAN_B 256
#define NBLK ((NN + SCAN_B - 1) / SCAN_B)  // 196

#define GEMM_THREADS 512
#define GEMM_ROWS 128                       // rows per block (4 rowgroups x 32)
#define GEMM_BLOCKS ((NN + GEMM_ROWS - 1) / GEMM_ROWS)  // 391
#define SCAT_BLOCKS ((EE + GEMM_THREADS - 1) / GEMM_THREADS)  // 1563
#define FUSED_BLOCKS (GEMM_BLOCKS * 5)      // 1955: bid%5==0 -> gemm, else scatter

// Scratch (no allocation allowed -> __device__ globals)
__device__ float g_h[NN * 128];
__device__ float g_agg[NN * 128];
__device__ int g_src[EE];
__device__ int g_dst[EE];
__device__ int g_csr[EE];
__device__ int g_cnt[NN];
__device__ int g_rowptr[NN + 1];
__device__ int g_cursor[NN];
__device__ float g_dinv[NN];
__device__ int g_is64;
__device__ int g_bsum[NBLK];
__device__ int g_boff[NBLK];

// ---------------------------------------------------------------------------
// Packed fp32x2 helpers (Blackwell 2x FP32 path; PTX-only, ptxas won't emit)
__device__ __forceinline__ unsigned long long pack2(float a, float b) {
    unsigned long long r;
    asm("mov.b64 %0, {%1, %2};" : "=l"(r) : "f"(a), "f"(b));
    return r;
}
__device__ __forceinline__ void unpack2(unsigned long long v, float& a, float& b) {
    asm("mov.b64 {%0, %1}, %2;" : "=f"(a), "=f"(b) : "l"(v));
}
__device__ __forceinline__ unsigned long long ffma2(unsigned long long a,
                                                    unsigned long long b,
                                                    unsigned long long c) {
    unsigned long long d;
    asm("fma.rn.f32x2 %0, %1, %2, %3;" : "=l"(d) : "l"(a), "l"(b), "l"(c));
    return d;
}

// ---------------------------------------------------------------------------
// zero counts + edge dtype detect (int64 LE < 2^31 has every odd word == 0)
__global__ void zero_detect_kernel() {
    int i = blockIdx.x * blockDim.x + threadIdx.x;
    if (i < NN) g_cnt[i] = 0;
    if (i == 0) {
        // done by thread 0 while others zero; separate kernel boundary before use
    }
}
__global__ void detect_kernel(const void* ei) {
    if (threadIdx.x == 0) {
        const int* w = (const int*)ei;
        int all0 = 1;
#pragma unroll 1
        for (int i = 1; i < 256; i += 2) all0 &= (w[i] == 0);
        g_is64 = all0;
    }
}

// Normalize edges to int32 + in-degree histogram (targets = edge_index[1]).
__global__ void convert_hist_kernel(const void* ei) {
    int i = blockIdx.x * blockDim.x + threadIdx.x;
    if (i >= EE) return;
    int s, d;
    if (g_is64) {
        const long long* p = (const long long*)ei;
        s = (int)p[i];
        d = (int)p[EE + i];
    } else {
        const int* p = (const int*)ei;
        s = p[i];
        d = p[EE + i];
    }
    g_src[i] = s;
    g_dst[i] = d;
    atomicAdd(&g_cnt[d], 1);
}

// ---------------------------------------------------------------------------
// Hierarchical exclusive scan over g_cnt (3 tiny kernels, all-SM parallel).
__global__ void bsum_kernel() {
    __shared__ int sw[8];
    int i = blockIdx.x * SCAN_B + threadIdx.x;
    int v = (i < NN) ? g_cnt[i] : 0;
#pragma unroll
    for (int o = 16; o > 0; o >>= 1) v += __shfl_down_sync(~0u, v, o);
    int lane = threadIdx.x & 31, w = threadIdx.x >> 5;
    if (lane == 0) sw[w] = v;
    __syncthreads();
    if (threadIdx.x < 8) {
        int s = sw[threadIdx.x];
#pragma unroll
        for (int o = 4; o > 0; o >>= 1) s += __shfl_down_sync(0xff, s, o);
        if (threadIdx.x == 0) g_bsum[blockIdx.x] = s;
    }
}

__global__ void boff_kernel() {
    __shared__ int sm[256];
    int tid = threadIdx.x;
    int v = (tid < NBLK) ? g_bsum[tid] : 0;
    sm[tid] = v;
    __syncthreads();
    for (int d = 1; d < 256; d <<= 1) {
        int t = (tid >= d) ? sm[tid - d] : 0;
        __syncthreads();
        sm[tid] += t;
        __syncthreads();
    }
    if (tid < NBLK) g_boff[tid] = sm[tid] - v;  // exclusive
    if (tid == 255) g_rowptr[NN] = sm[255];
}

__global__ void scanwrite_kernel() {
    __shared__ int swarp[8];
    int tid = threadIdx.x;
    int i = blockIdx.x * SCAN_B + tid;
    int c = (i < NN) ? g_cnt[i] : 0;
    int v = c;
    int lane = tid & 31, w = tid >> 5;
#pragma unroll
    for (int o = 1; o < 32; o <<= 1) {
        int t = __shfl_up_sync(~0u, v, o);
        if (lane >= o) v += t;
    }
    if (lane == 31) swarp[w] = v;
    __syncthreads();
    if (tid < 8) {
        int s = swarp[tid];
#pragma unroll
        for (int o = 1; o < 8; o <<= 1) {
            int t = __shfl_up_sync(0xff, s, o);
            if (tid >= o) s += t;
        }
        swarp[tid] = s;
    }
    __syncthreads();
    int excl = v - c + (w > 0 ? swarp[w - 1] : 0) + g_boff[blockIdx.x];
    if (i < NN) {
        g_rowptr[i] = excl;
        g_cursor[i] = excl;
        g_dinv[i] = rsqrtf((float)c + 1.0f);
    }
}

// ---------------------------------------------------------------------------
// FFMA2 GEMM: [NN,128] x [128,128] -> out. 512 threads = 16 warps =
// 4 rowgroups x 4 colgroups. Each lane: 1 row x 32 cols (16 packed u64 accs).
// X chunked into registers (no x smem); W broadcast from smem (uniform-addr
// LDS.128 = 1 crossbar phase). Optionally fused with CSR scatter blocks
// (bid % 5 != 0) to overlap atomic-bound scatter with FMA-bound GEMM.
// Split mode (B1 != null): B = [B0 | B1] (128x64 each), outputs O0/O1.
__global__ void __launch_bounds__(GEMM_THREADS, 1) gemm_fused_kernel(
    const float* __restrict__ X, const float* __restrict__ B0,
    const float* __restrict__ B1, const float* __restrict__ bias0,
    const float* __restrict__ bias1, float* __restrict__ O0,
    float* __restrict__ O1, int do_relu, int with_scatter) {
    int tid = threadIdx.x;
    int bid = blockIdx.x;

    if (with_scatter && (bid % 5) != 0) {
        // ---- scatter path ----
        int sbid = (bid / 5) * 4 + (bid % 5) - 1;
        int i = sbid * GEMM_THREADS + tid;
        if (i < EE) {
            int d = g_dst[i];
            int p = atomicAdd(&g_cursor[d], 1);
            g_csr[p] = g_src[i];
        }
        return;
    }
    int gb = with_scatter ? (bid / 5) : bid;

    extern __shared__ float Wsm[];  // 128x128
    // cooperative W load
    for (int idx = tid; idx < 128 * 128; idx += GEMM_THREADS) {
        float v;
        if (B1) {
            int k = idx >> 7, n = idx & 127;
            v = (n < 64) ? B0[(k << 6) + n] : B1[(k << 6) + n - 64];
        } else {
            v = B0[idx];
        }
        Wsm[idx] = v;
    }
    __syncthreads();

    int warp = tid >> 5, lane = tid & 31;
    int rowgrp = warp >> 2, colgrp = warp & 3;
    int row = gb * GEMM_ROWS + rowgrp * 32 + lane;
    int rowL = (row < NN) ? row : (NN - 1);
    int c0 = colgrp * 32;

    unsigned long long acc[16];
#pragma unroll
    for (int p = 0; p < 16; p++) acc[p] = pack2(0.f, 0.f);

#pragma unroll 1
    for (int kc = 0; kc < 128; kc += 32) {
        float4 xr[8];
#pragma unroll
        for (int j = 0; j < 8; j++)
            xr[j] = *(const float4*)(X + (size_t)rowL * 128 + kc + j * 4);
#pragma unroll
        for (int j = 0; j < 8; j++) {
            float xv[4] = {xr[j].x, xr[j].y, xr[j].z, xr[j].w};
#pragma unroll
            for (int kk = 0; kk < 4; kk++) {
                int k = kc + j * 4 + kk;
                unsigned long long xp = pack2(xv[kk], xv[kk]);
                const ulonglong2* wrow =
                    (const ulonglong2*)(Wsm + k * 128 + c0);
#pragma unroll
                for (int p = 0; p < 8; p++) {
                    ulonglong2 wp = wrow[p];  // uniform addr -> broadcast
                    acc[2 * p] = ffma2(xp, wp.x, acc[2 * p]);
                    acc[2 * p + 1] = ffma2(xp, wp.y, acc[2 * p + 1]);
                }
            }
        }
    }

    if (row >= NN) return;

    float ob[32];
#pragma unroll
    for (int p = 0; p < 16; p++) unpack2(acc[p], ob[2 * p], ob[2 * p + 1]);

#pragma unroll
    for (int q = 0; q < 8; q++) {
        int col = c0 + q * 4;
        float4 o = make_float4(ob[4 * q], ob[4 * q + 1], ob[4 * q + 2],
                               ob[4 * q + 3]);
        float4 bi = make_float4(0.f, 0.f, 0.f, 0.f);
        if (bias0) {
            if (B1)
                bi = (col < 64) ? *(const float4*)(bias0 + col)
                                : *(const float4*)(bias1 + col - 64);
            else
                bi = *(const float4*)(bias0 + col);
        }
        o.x += bi.x; o.y += bi.y; o.z += bi.z; o.w += bi.w;
        if (do_relu) {
            o.x = fmaxf(o.x, 0.f); o.y = fmaxf(o.y, 0.f);
            o.z = fmaxf(o.z, 0.f); o.w = fmaxf(o.w, 0.f);
        }
        if (B1) {
            if (col < 64)
                *(float4*)(O0 + (size_t)row * 64 + col) = o;
            else
                *(float4*)(O1 + (size_t)row * 64 + col - 64) = o;
        } else {
            *(float4*)(O0 + (size_t)row * 128 + col) = o;
        }
    }
}

// ---------------------------------------------------------------------------
// Aggregation: OUT[c] = dinv[c]*(sum_{r in in(c)} dinv[r]*H[r]) + dinv[c]^2*H[c]
// One warp per node, 4 channels per lane (float4). Optional bias+relu epilogue.
__global__ void agg_kernel(const float* __restrict__ H, float* __restrict__ OUT,
                           const float* __restrict__ bias, int do_relu) {
    int gw = (blockIdx.x * blockDim.x + threadIdx.x) >> 5;
    if (gw >= NN) return;
    int lane = threadIdx.x & 31;
    int node = gw;
    int s = g_rowptr[node], e = g_rowptr[node + 1];
    float ax = 0.f, ay = 0.f, az = 0.f, aw = 0.f;
    for (int j = s; j < e; j++) {
        int src = g_csr[j];
        float wgt = g_dinv[src];
        float4 v = *(const float4*)(H + (size_t)src * 128 + lane * 4);
        ax += wgt * v.x; ay += wgt * v.y; az += wgt * v.z; aw += wgt * v.w;
    }
    float dc = g_dinv[node];
    float dc2 = dc * dc;
    float4 sv = *(const float4*)(H + (size_t)node * 128 + lane * 4);
    ax = dc * ax + dc2 * sv.x;
    ay = dc * ay + dc2 * sv.y;
    az = dc * az + dc2 * sv.z;
    aw = dc * aw + dc2 * sv.w;
    if (bias) {
        float4 bi = *(const float4*)(bias + lane * 4);
        ax += bi.x; ay += bi.y; az += bi.z; aw += bi.w;
    }
    if (do_relu) {
        ax = fmaxf(ax, 0.f); ay = fmaxf(ay, 0.f);
        az = fmaxf(az, 0.f); aw = fmaxf(aw, 0.f);
    }
    *(float4*)(OUT + (size_t)node * 128 + lane * 4) =
        make_float4(ax, ay, az, aw);
}

// ---------------------------------------------------------------------------
extern "C" void kernel_launch(void* const* d_in, const int* in_sizes, int n_in,
                              void* d_out, int out_size) {
    const float* x = (const float*)d_in[0];
    const void* ei = d_in[1];
    const float* W1 = (const float*)d_in[2];
    const float* b1 = (const float*)d_in[3];
    const float* W2 = (const float*)d_in[4];
    const float* b2 = (const float*)d_in[5];
    const float* W3 = (const float*)d_in[6];
    const float* b3 = (const float*)d_in[7];
    float* out = (float*)d_out;

    float* ph;
    float* pagg;
    cudaGetSymbolAddress((void**)&ph, g_h);
    cudaGetSymbolAddress((void**)&pagg, g_agg);

    const size_t smem = 128 * 128 * sizeof(float);  // 64 KB
    cudaFuncSetAttribute(gemm_fused_kernel,
                         cudaFuncAttributeMaxDynamicSharedMemorySize,
                         (int)smem);

    // CSR build (recomputed every replay; graph-capture safe, no allocs)
    detect_kernel<<<1, 32>>>(ei);
    zero_detect_kernel<<<NBLK, 256>>>();
    convert_hist_kernel<<<(EE + 255) / 256, 256>>>(ei);
    bsum_kernel<<<NBLK, SCAN_B>>>();
    boff_kernel<<<1, 256>>>();
    scanwrite_kernel<<<NBLK, SCAN_B>>>();

    int ablocks = (NN * 32 + 255) / 256;

    // h = x @ W1  (fused with CSR scatter: overlap FMA-bound GEMM with
    // atomic-bound scatter in one launch)
    gemm_fused_kernel<<<FUSED_BLOCKS, GEMM_THREADS, smem>>>(
        x, W1, nullptr, nullptr, nullptr, ph, nullptr, 0, 1);
    // hidden = relu(A h + b1)
    agg_kernel<<<ablocks, 256>>>(ph, pagg, b1, 1);
    // aggH = A hidden  (shared by both heads)
    agg_kernel<<<ablocks, 256>>>(pagg, ph, nullptr, 0);
    // x1 = relu(aggH @ W2 + b2), x2 = relu(aggH @ W3 + b3)
    gemm_fused_kernel<<<GEMM_BLOCKS, GEMM_THREADS, smem>>>(
        ph, W2, W3, b2, b3, out, out + (size_t)NN * 64, 1, 0);
}

// round 8
// speedup vs baseline: 1.1218x; 1.1218x over previous
#include <cuda_runtime.h>

#define NN 50000
#define EE 800000
#define SCAN_B 256
#define NBLK ((NN + SCAN_B - 1) / SCAN_B)  // 196

// Scratch (no allocation allowed -> __device__ globals)
__device__ float g_h[NN * 128];
__device__ float g_agg[NN * 128];
__device__ int g_csr[EE];
__device__ int g_cnt[NN];
__device__ int g_rowptr[NN + 1];
__device__ int g_cursor[NN];
__device__ float g_dinv[NN];
__device__ int g_is64;
__device__ int g_bsum[NBLK];
__device__ int g_boff[NBLK];

// ---------------------------------------------------------------------------
// Edge dtype detection: int64 little-endian with values < 2^31 has every odd
// 32-bit word == 0. Random int32 node ids make that astronomically unlikely.
__global__ void detect_kernel(const void* ei) {
    if (threadIdx.x == 0) {
        const int* w = (const int*)ei;
        int all0 = 1;
#pragma unroll 1
        for (int i = 1; i < 256; i += 2) all0 &= (w[i] == 0);
        g_is64 = all0;
    }
}

__global__ void zero_cnt_kernel() {
    int i = blockIdx.x * blockDim.x + threadIdx.x;
    if (i < NN) g_cnt[i] = 0;
}

// In-degree histogram, reading edge_index[1] (targets) directly.
__global__ void hist_kernel(const void* ei) {
    int i = blockIdx.x * blockDim.x + threadIdx.x;
    if (i >= EE) return;
    int d;
    if (g_is64) {
        d = (int)((const long long*)ei)[EE + i];
    } else {
        d = ((const int*)ei)[EE + i];
    }
    atomicAdd(&g_cnt[d], 1);
}

// ---------------------------------------------------------------------------
// Hierarchical exclusive scan over g_cnt (3 tiny kernels, all-SM parallel).
__global__ void bsum_kernel() {
    __shared__ int sw[8];
    int i = blockIdx.x * SCAN_B + threadIdx.x;
    int v = (i < NN) ? g_cnt[i] : 0;
#pragma unroll
    for (int o = 16; o > 0; o >>= 1) v += __shfl_down_sync(~0u, v, o);
    int lane = threadIdx.x & 31, w = threadIdx.x >> 5;
    if (lane == 0) sw[w] = v;
    __syncthreads();
    if (threadIdx.x < 8) {
        int s = sw[threadIdx.x];
#pragma unroll
        for (int o = 4; o > 0; o >>= 1) s += __shfl_down_sync(0xff, s, o);
        if (threadIdx.x == 0) g_bsum[blockIdx.x] = s;
    }
}

__global__ void boff_kernel() {
    __shared__ int sm[256];
    int tid = threadIdx.x;
    int v = (tid < NBLK) ? g_bsum[tid] : 0;
    sm[tid] = v;
    __syncthreads();
    for (int d = 1; d < 256; d <<= 1) {
        int t = (tid >= d) ? sm[tid - d] : 0;
        __syncthreads();
        sm[tid] += t;
        __syncthreads();
    }
    if (tid < NBLK) g_boff[tid] = sm[tid] - v;  // exclusive
    if (tid == 255) g_rowptr[NN] = sm[255];
}

__global__ void scanwrite_kernel() {
    __shared__ int swarp[8];
    int tid = threadIdx.x;
    int i = blockIdx.x * SCAN_B + tid;
    int c = (i < NN) ? g_cnt[i] : 0;
    int v = c;
    int lane = tid & 31, w = tid >> 5;
#pragma unroll
    for (int o = 1; o < 32; o <<= 1) {
        int t = __shfl_up_sync(~0u, v, o);
        if (lane >= o) v += t;
    }
    if (lane == 31) swarp[w] = v;
    __syncthreads();
    if (tid < 8) {
        int s = swarp[tid];
#pragma unroll
        for (int o = 1; o < 8; o <<= 1) {
            int t = __shfl_up_sync(0xff, s, o);
            if (tid >= o) s += t;
        }
        swarp[tid] = s;
    }
    __syncthreads();
    int excl = v - c + (w > 0 ? swarp[w - 1] : 0) + g_boff[blockIdx.x];
    if (i < NN) {
        g_rowptr[i] = excl;
        g_cursor[i] = excl;
        g_dinv[i] = rsqrtf((float)c + 1.0f);
    }
}

// Scatter sources into CSR slots, reading edge_index directly.
__global__ void scatter_kernel(const void* ei) {
    int i = blockIdx.x * blockDim.x + threadIdx.x;
    if (i >= EE) return;
    int s, d;
    if (g_is64) {
        const long long* p = (const long long*)ei;
        s = (int)p[i];
        d = (int)p[EE + i];
    } else {
        const int* p = (const int*)ei;
        s = p[i];
        d = p[EE + i];
    }
    int pos = atomicAdd(&g_cursor[d], 1);
    g_csr[pos] = s;
}

// ---------------------------------------------------------------------------
// GEMM (R5-proven, FMA-pipe-bound at fp32 floor): [NN,128] x [128,128].
// W resident in smem. 8 warps/block, each warp 4 rows x 128 cols.
// If B1 != null: B = [B0 (128x64) | B1 (128x64)], outputs split O0/O1.
__global__ void __launch_bounds__(256, 2) gemm128_kernel(
    const float* __restrict__ X, const float* __restrict__ B0,
    const float* __restrict__ B1, const float* __restrict__ bias0,
    const float* __restrict__ bias1, float* __restrict__ O0,
    float* __restrict__ O1, int do_relu) {
    extern __shared__ float sm[];
    float* Wsm = sm;              // 128*128 floats
    float* xs = sm + 128 * 128;   // 8 warps * 4 rows * 128 floats
    int tid = threadIdx.x, w = tid >> 5, lane = tid & 31;

    for (int idx = tid; idx < 128 * 128; idx += 256) {
        float v;
        if (B1) {
            int k = idx >> 7, n = idx & 127;
            v = (n < 64) ? B0[(k << 6) + n] : B1[(k << 6) + n - 64];
        } else {
            v = B0[idx];
        }
        Wsm[idx] = v;
    }
    __syncthreads();

    int row0 = (blockIdx.x * 8 + w) * 4;
    if (row0 >= NN) return;
    float* xw = xs + w * 4 * 128;

#pragma unroll
    for (int r = 0; r < 4; r++) {
        int row = row0 + r;
        float4 v = (row < NN) ? *(const float4*)(X + (size_t)row * 128 + lane * 4)
                              : make_float4(0.f, 0.f, 0.f, 0.f);
        *(float4*)(xw + r * 128 + lane * 4) = v;
    }
    __syncwarp();

    float4 a0 = make_float4(0.f, 0.f, 0.f, 0.f), a1 = a0, a2 = a0, a3 = a0;
#pragma unroll 16
    for (int k = 0; k < 128; k++) {
        float4 wv = *(float4*)(Wsm + k * 128 + lane * 4);
        float x0 = xw[0 * 128 + k];
        float x1 = xw[1 * 128 + k];
        float x2 = xw[2 * 128 + k];
        float x3 = xw[3 * 128 + k];
        a0.x += x0 * wv.x; a0.y += x0 * wv.y; a0.z += x0 * wv.z; a0.w += x0 * wv.w;
        a1.x += x1 * wv.x; a1.y += x1 * wv.y; a1.z += x1 * wv.z; a1.w += x1 * wv.w;
        a2.x += x2 * wv.x; a2.y += x2 * wv.y; a2.z += x2 * wv.z; a2.w += x2 * wv.w;
        a3.x += x3 * wv.x; a3.y += x3 * wv.y; a3.z += x3 * wv.z; a3.w += x3 * wv.w;
    }

    int col = lane * 4;
    float4 bi = make_float4(0.f, 0.f, 0.f, 0.f);
    if (bias0) {
        if (B1)
            bi = (col < 64) ? *(const float4*)(bias0 + col)
                            : *(const float4*)(bias1 + col - 64);
        else
            bi = *(const float4*)(bias0 + col);
    }
    float4 accs[4] = {a0, a1, a2, a3};
#pragma unroll
    for (int r = 0; r < 4; r++) {
        int row = row0 + r;
        if (row >= NN) break;
        float4 o = accs[r];
        o.x += bi.x; o.y += bi.y; o.z += bi.z; o.w += bi.w;
        if (do_relu) {
            o.x = fmaxf(o.x, 0.f); o.y = fmaxf(o.y, 0.f);
            o.z = fmaxf(o.z, 0.f); o.w = fmaxf(o.w, 0.f);
        }
        if (B1) {
            if (col < 64)
                *(float4*)(O0 + (size_t)row * 64 + col) = o;
            else
                *(float4*)(O1 + (size_t)row * 64 + col - 64) = o;
        } else {
            *(float4*)(O0 + (size_t)row * 128 + col) = o;
        }
    }
}

// ---------------------------------------------------------------------------
// Aggregation: OUT[c] = dinv[c]*(sum_{r in in(c)} dinv[r]*H[r]) + dinv[c]^2*H[c]
// One warp per node, 4 channels per lane (float4). Software-pipelined index
// load breaks the csr->H dependent-load chain.
__global__ void agg_kernel(const float* __restrict__ H, float* __restrict__ OUT,
                           const float* __restrict__ bias, int do_relu) {
    int gw = (blockIdx.x * blockDim.x + threadIdx.x) >> 5;
    if (gw >= NN) return;
    int lane = threadIdx.x & 31;
    int node = gw;
    int s = g_rowptr[node], e = g_rowptr[node + 1];
    float ax = 0.f, ay = 0.f, az = 0.f, aw = 0.f;

    int src_nxt = (s < e) ? g_csr[s] : 0;
    float w_nxt = (s < e) ? g_dinv[src_nxt] : 0.f;
#pragma unroll 1
    for (int j = s; j < e; j++) {
        int src = src_nxt;
        float wgt = w_nxt;
        int jn = j + 1;
        if (jn < e) {
            src_nxt = g_csr[jn];      // issued before dependent H gather
            w_nxt = g_dinv[src_nxt];
        }
        float4 v = *(const float4*)(H + (size_t)src * 128 + lane * 4);
        ax += wgt * v.x; ay += wgt * v.y; az += wgt * v.z; aw += wgt * v.w;
    }
    float dc = g_dinv[node];
    float dc2 = dc * dc;
    float4 sv = *(const float4*)(H + (size_t)node * 128 + lane * 4);
    ax = dc * ax + dc2 * sv.x;
    ay = dc * ay + dc2 * sv.y;
    az = dc * az + dc2 * sv.z;
    aw = dc * aw + dc2 * sv.w;
    if (bias) {
        float4 bi = *(const float4*)(bias + lane * 4);
        ax += bi.x; ay += bi.y; az += bi.z; aw += bi.w;
    }
    if (do_relu) {
        ax = fmaxf(ax, 0.f); ay = fmaxf(ay, 0.f);
        az = fmaxf(az, 0.f); aw = fmaxf(aw, 0.f);
    }
    *(float4*)(OUT + (size_t)node * 128 + lane * 4) =
        make_float4(ax, ay, az, aw);
}

// ---------------------------------------------------------------------------
extern "C" void kernel_launch(void* const* d_in, const int* in_sizes, int n_in,
                              void* d_out, int out_size) {
    const float* x = (const float*)d_in[0];
    const void* ei = d_in[1];
    const float* W1 = (const float*)d_in[2];
    const float* b1 = (const float*)d_in[3];
    const float* W2 = (const float*)d_in[4];
    const float* b2 = (const float*)d_in[5];
    const float* W3 = (const float*)d_in[6];
    const float* b3 = (const float*)d_in[7];
    float* out = (float*)d_out;

    float* ph;
    float* pagg;
    cudaGetSymbolAddress((void**)&ph, g_h);
    cudaGetSymbolAddress((void**)&pagg, g_agg);

    const size_t smem = (128 * 128 + 8 * 4 * 128) * sizeof(float);  // 80 KB
    cudaFuncSetAttribute(gemm128_kernel,
                         cudaFuncAttributeMaxDynamicSharedMemorySize,
                         (int)smem);

    // CSR build (recomputed every replay; graph-capture safe, no allocs,
    // no stream/event creation — single stream only)
    detect_kernel<<<1, 32>>>(ei);
    zero_cnt_kernel<<<NBLK, 256>>>();
    hist_kernel<<<(EE + 255) / 256, 256>>>(ei);
    bsum_kernel<<<NBLK, SCAN_B>>>();
    boff_kernel<<<1, 256>>>();
    scanwrite_kernel<<<NBLK, SCAN_B>>>();
    scatter_kernel<<<(EE + 255) / 256, 256>>>(ei);

    int gblocks = (NN + 31) / 32;
    int ablocks = (NN * 32 + 255) / 256;

    // h = x @ W1
    gemm128_kernel<<<gblocks, 256, smem>>>(x, W1, nullptr, nullptr, nullptr,
                                           ph, nullptr, 0);
    // hidden = relu(A h + b1)
    agg_kernel<<<ablocks, 256>>>(ph, pagg, b1, 1);
    // aggH = A hidden  (shared by both heads)
    agg_kernel<<<ablocks, 256>>>(pagg, ph, nullptr, 0);
    // x1 = relu(aggH @ W2 + b2), x2 = relu(aggH @ W3 + b3)
    gemm128_kernel<<<gblocks, 256, smem>>>(ph, W2, W3, b2, b3, out,
                                           out + (size_t)NN * 64, 1);
}

// round 9
// speedup vs baseline: 1.2033x; 1.0727x over previous
#include <cuda_runtime.h>

#define NN 50000
#define EE 800000
#define SCAN_B 256
#define NBLK ((NN + SCAN_B - 1) / SCAN_B)  // 196

// Scratch (no allocation allowed -> __device__ globals)
__device__ float g_h[NN * 128];
__device__ float g_agg[NN * 128];
__device__ int g_csr[EE];
__device__ int g_cnt[NN];
__device__ int g_rowptr[NN + 1];
__device__ int g_cursor[NN];
__device__ float g_dinv[NN];
__device__ int g_is64;
__device__ int g_bsum[NBLK];
__device__ int g_boff[NBLK];

// ---------------------------------------------------------------------------
// Edge dtype detection: int64 little-endian with values < 2^31 has every odd
// 32-bit word == 0. Random int32 node ids make that astronomically unlikely.
__global__ void detect_kernel(const void* ei) {
    if (threadIdx.x == 0) {
        const int* w = (const int*)ei;
        int all0 = 1;
#pragma unroll 1
        for (int i = 1; i < 256; i += 2) all0 &= (w[i] == 0);
        g_is64 = all0;
    }
}

__global__ void zero_cnt_kernel() {
    int i = blockIdx.x * blockDim.x + threadIdx.x;
    if (i < NN) g_cnt[i] = 0;
}

// In-degree histogram, reading edge_index[1] (targets) directly.
__global__ void hist_kernel(const void* ei) {
    int i = blockIdx.x * blockDim.x + threadIdx.x;
    if (i >= EE) return;
    int d;
    if (g_is64) {
        d = (int)((const long long*)ei)[EE + i];
    } else {
        d = ((const int*)ei)[EE + i];
    }
    atomicAdd(&g_cnt[d], 1);
}

// ---------------------------------------------------------------------------
// Hierarchical exclusive scan over g_cnt (3 tiny kernels, all-SM parallel).
__global__ void bsum_kernel() {
    __shared__ int sw[8];
    int i = blockIdx.x * SCAN_B + threadIdx.x;
    int v = (i < NN) ? g_cnt[i] : 0;
#pragma unroll
    for (int o = 16; o > 0; o >>= 1) v += __shfl_down_sync(~0u, v, o);
    int lane = threadIdx.x & 31, w = threadIdx.x >> 5;
    if (lane == 0) sw[w] = v;
    __syncthreads();
    if (threadIdx.x < 8) {
        int s = sw[threadIdx.x];
#pragma unroll
        for (int o = 4; o > 0; o >>= 1) s += __shfl_down_sync(0xff, s, o);
        if (threadIdx.x == 0) g_bsum[blockIdx.x] = s;
    }
}

__global__ void boff_kernel() {
    __shared__ int sm[256];
    int tid = threadIdx.x;
    int v = (tid < NBLK) ? g_bsum[tid] : 0;
    sm[tid] = v;
    __syncthreads();
    for (int d = 1; d < 256; d <<= 1) {
        int t = (tid >= d) ? sm[tid - d] : 0;
        __syncthreads();
        sm[tid] += t;
        __syncthreads();
    }
    if (tid < NBLK) g_boff[tid] = sm[tid] - v;  // exclusive
    if (tid == 255) g_rowptr[NN] = sm[255];
}

__global__ void scanwrite_kernel() {
    __shared__ int swarp[8];
    int tid = threadIdx.x;
    int i = blockIdx.x * SCAN_B + tid;
    int c = (i < NN) ? g_cnt[i] : 0;
    int v = c;
    int lane = tid & 31, w = tid >> 5;
#pragma unroll
    for (int o = 1; o < 32; o <<= 1) {
        int t = __shfl_up_sync(~0u, v, o);
        if (lane >= o) v += t;
    }
    if (lane == 31) swarp[w] = v;
    __syncthreads();
    if (tid < 8) {
        int s = swarp[tid];
#pragma unroll
        for (int o = 1; o < 8; o <<= 1) {
            int t = __shfl_up_sync(0xff, s, o);
            if (tid >= o) s += t;
        }
        swarp[tid] = s;
    }
    __syncthreads();
    int excl = v - c + (w > 0 ? swarp[w - 1] : 0) + g_boff[blockIdx.x];
    if (i < NN) {
        g_rowptr[i] = excl;
        g_cursor[i] = excl;
        g_dinv[i] = rsqrtf((float)c + 1.0f);
    }
}

// ---------------------------------------------------------------------------
// GEMM (R5-proven, FMA-pipe-bound at fp32 floor): [NN,128] x [128,128].
// W resident in smem. 8 warps/block, each warp 4 rows x 128 cols.
// If B1 != null: B = [B0 (128x64) | B1 (128x64)], outputs split O0/O1.
// If ei != null: thread-level fused CSR scatter — each thread grid-strides
// over ~2 edges BEFORE its GEMM work. Same blocks/smem as pure GEMM, so no
// occupancy penalty (R6's block-specialization mistake); the atomic-bound
// scatter hides under the FMA-bound GEMM.
__global__ void __launch_bounds__(256, 2) gemm128_kernel(
    const float* __restrict__ X, const float* __restrict__ B0,
    const float* __restrict__ B1, const float* __restrict__ bias0,
    const float* __restrict__ bias1, float* __restrict__ O0,
    float* __restrict__ O1, int do_relu, const void* ei) {
    extern __shared__ float sm[];
    float* Wsm = sm;              // 128*128 floats
    float* xs = sm + 128 * 128;   // 8 warps * 4 rows * 128 floats
    int tid = threadIdx.x, w = tid >> 5, lane = tid & 31;

    if (ei) {  // fused scatter: ~2 edges per thread
        int stride = gridDim.x * blockDim.x;
        if (g_is64) {
            const long long* p = (const long long*)ei;
            for (int i = blockIdx.x * blockDim.x + tid; i < EE; i += stride) {
                int s = (int)p[i];
                int d = (int)p[EE + i];
                int pos = atomicAdd(&g_cursor[d], 1);
                g_csr[pos] = s;
            }
        } else {
            const int* p = (const int*)ei;
            for (int i = blockIdx.x * blockDim.x + tid; i < EE; i += stride) {
                int s = p[i];
                int d = p[EE + i];
                int pos = atomicAdd(&g_cursor[d], 1);
                g_csr[pos] = s;
            }
        }
    }

    for (int idx = tid; idx < 128 * 128; idx += 256) {
        float v;
        if (B1) {
            int k = idx >> 7, n = idx & 127;
            v = (n < 64) ? B0[(k << 6) + n] : B1[(k << 6) + n - 64];
        } else {
            v = B0[idx];
        }
        Wsm[idx] = v;
    }
    __syncthreads();

    int row0 = (blockIdx.x * 8 + w) * 4;
    if (row0 >= NN) return;
    float* xw = xs + w * 4 * 128;

#pragma unroll
    for (int r = 0; r < 4; r++) {
        int row = row0 + r;
        float4 v = (row < NN) ? *(const float4*)(X + (size_t)row * 128 + lane * 4)
                              : make_float4(0.f, 0.f, 0.f, 0.f);
        *(float4*)(xw + r * 128 + lane * 4) = v;
    }
    __syncwarp();

    float4 a0 = make_float4(0.f, 0.f, 0.f, 0.f), a1 = a0, a2 = a0, a3 = a0;
#pragma unroll 16
    for (int k = 0; k < 128; k++) {
        float4 wv = *(float4*)(Wsm + k * 128 + lane * 4);
        float x0 = xw[0 * 128 + k];
        float x1 = xw[1 * 128 + k];
        float x2 = xw[2 * 128 + k];
        float x3 = xw[3 * 128 + k];
        a0.x += x0 * wv.x; a0.y += x0 * wv.y; a0.z += x0 * wv.z; a0.w += x0 * wv.w;
        a1.x += x1 * wv.x; a1.y += x1 * wv.y; a1.z += x1 * wv.z; a1.w += x1 * wv.w;
        a2.x += x2 * wv.x; a2.y += x2 * wv.y; a2.z += x2 * wv.z; a2.w += x2 * wv.w;
        a3.x += x3 * wv.x; a3.y += x3 * wv.y; a3.z += x3 * wv.z; a3.w += x3 * wv.w;
    }

    int col = lane * 4;
    float4 bi = make_float4(0.f, 0.f, 0.f, 0.f);
    if (bias0) {
        if (B1)
            bi = (col < 64) ? *(const float4*)(bias0 + col)
                            : *(const float4*)(bias1 + col - 64);
        else
            bi = *(const float4*)(bias0 + col);
    }
    float4 accs[4] = {a0, a1, a2, a3};
#pragma unroll
    for (int r = 0; r < 4; r++) {
        int row = row0 + r;
        if (row >= NN) break;
        float4 o = accs[r];
        o.x += bi.x; o.y += bi.y; o.z += bi.z; o.w += bi.w;
        if (do_relu) {
            o.x = fmaxf(o.x, 0.f); o.y = fmaxf(o.y, 0.f);
            o.z = fmaxf(o.z, 0.f); o.w = fmaxf(o.w, 0.f);
        }
        if (B1) {
            if (col < 64)
                *(float4*)(O0 + (size_t)row * 64 + col) = o;
            else
                *(float4*)(O1 + (size_t)row * 64 + col - 64) = o;
        } else {
            *(float4*)(O0 + (size_t)row * 128 + col) = o;
        }
    }
}

// ---------------------------------------------------------------------------
// Aggregation (R5-proven loop — ptxas unrolls the gather for MLP; do NOT
// add unroll pragmas or manual prefetch here, R8 showed that regresses).
// OUT[c] = dinv[c]*(sum_{r in in(c)} dinv[r]*H[r]) + dinv[c]^2*H[c]
__global__ void agg_kernel(const float* __restrict__ H, float* __restrict__ OUT,
                           const float* __restrict__ bias, int do_relu) {
    int gw = (blockIdx.x * blockDim.x + threadIdx.x) >> 5;
    if (gw >= NN) return;
    int lane = threadIdx.x & 31;
    int node = gw;
    int s = g_rowptr[node], e = g_rowptr[node + 1];
    float ax = 0.f, ay = 0.f, az = 0.f, aw = 0.f;
    for (int j = s; j < e; j++) {
        int src = g_csr[j];
        float wgt = g_dinv[src];
        float4 v = *(const float4*)(H + (size_t)src * 128 + lane * 4);
        ax += wgt * v.x; ay += wgt * v.y; az += wgt * v.z; aw += wgt * v.w;
    }
    float dc = g_dinv[node];
    float dc2 = dc * dc;
    float4 sv = *(const float4*)(H + (size_t)node * 128 + lane * 4);
    ax = dc * ax + dc2 * sv.x;
    ay = dc * ay + dc2 * sv.y;
    az = dc * az + dc2 * sv.z;
    aw = dc * aw + dc2 * sv.w;
    if (bias) {
        float4 bi = *(const float4*)(bias + lane * 4);
        ax += bi.x; ay += bi.y; az += bi.z; aw += bi.w;
    }
    if (do_relu) {
        ax = fmaxf(ax, 0.f); ay = fmaxf(ay, 0.f);
        az = fmaxf(az, 0.f); aw = fmaxf(aw, 0.f);
    }
    *(float4*)(OUT + (size_t)node * 128 + lane * 4) =
        make_float4(ax, ay, az, aw);
}

// ---------------------------------------------------------------------------
extern "C" void kernel_launch(void* const* d_in, const int* in_sizes, int n_in,
                              void* d_out, int out_size) {
    const float* x = (const float*)d_in[0];
    const void* ei = d_in[1];
    const float* W1 = (const float*)d_in[2];
    const float* b1 = (const float*)d_in[3];
    const float* W2 = (const float*)d_in[4];
    const float* b2 = (const float*)d_in[5];
    const float* W3 = (const float*)d_in[6];
    const float* b3 = (const float*)d_in[7];
    float* out = (float*)d_out;

    float* ph;
    float* pagg;
    cudaGetSymbolAddress((void**)&ph, g_h);
    cudaGetSymbolAddress((void**)&pagg, g_agg);

    const size_t smem = (128 * 128 + 8 * 4 * 128) * sizeof(float);  // 80 KB
    cudaFuncSetAttribute(gemm128_kernel,
                         cudaFuncAttributeMaxDynamicSharedMemorySize,
                         (int)smem);

    // CSR build prefix (scatter is fused into GEMM1 below)
    detect_kernel<<<1, 32>>>(ei);
    zero_cnt_kernel<<<NBLK, 256>>>();
    hist_kernel<<<(EE + 255) / 256, 256>>>(ei);
    bsum_kernel<<<NBLK, SCAN_B>>>();
    boff_kernel<<<1, 256>>>();
    scanwrite_kernel<<<NBLK, SCAN_B>>>();

    int gblocks = (NN + 31) / 32;
    int ablocks = (NN * 32 + 255) / 256;

    // h = x @ W1, with CSR scatter fused in (thread-level, same occupancy)
    gemm128_kernel<<<gblocks, 256, smem>>>(x, W1, nullptr, nullptr, nullptr,
                                           ph, nullptr, 0, ei);
    // hidden = relu(A h + b1)
    agg_kernel<<<ablocks, 256>>>(ph, pagg, b1, 1);
    // aggH = A hidden  (shared by both heads)
    agg_kernel<<<ablocks, 256>>>(pagg, ph, nullptr, 0);
    // x1 = relu(aggH @ W2 + b2), x2 = relu(aggH @ W3 + b3)
    gemm128_kernel<<<gblocks, 256, smem>>>(ph, W2, W3, b2, b3, out,
                                           out + (size_t)NN * 64, 1, nullptr);
}

// round 10
// speedup vs baseline: 1.2592x; 1.0464x over previous
#include <cuda_runtime.h>
#include <cuda_fp16.h>

#define NN 50000
#define EE 800000
#define SCAN_B 256
#define NBLK ((NN + SCAN_B - 1) / SCAN_B)  // 196

// Scratch (no allocation allowed -> __device__ globals)
__device__ float g_f32buf[NN * 128];   // fp32 staging (aggH for gemm2)
__device__ __half g_hh[NN * 128];      // h = x@W1, fp16
__device__ __half g_hid[NN * 128];     // hidden = relu(A h + b1), fp16
__device__ int g_csr[EE];
__device__ int g_cnt[NN];              // zero-init at load; self-zeroing per call
__device__ int g_rowptr[NN + 1];
__device__ int g_cursor[NN];
__device__ float g_dinv[NN];
__device__ int g_is64;
__device__ int g_bsum[NBLK];
__device__ int g_boff[NBLK];

// ---------------------------------------------------------------------------
// fp16/fp32 4-wide load/store helpers (compute is always fp32)
__device__ __forceinline__ float4 ld4(const float* p) {
    return *(const float4*)p;
}
__device__ __forceinline__ float4 ld4(const __half* p) {
    uint2 u = *(const uint2*)p;  // one 8B load
    __half2 h0 = *reinterpret_cast<__half2*>(&u.x);
    __half2 h1 = *reinterpret_cast<__half2*>(&u.y);
    float2 f0 = __half22float2(h0), f1 = __half22float2(h1);
    return make_float4(f0.x, f0.y, f1.x, f1.y);
}
__device__ __forceinline__ void st4(float* p, float4 v) {
    *(float4*)p = v;
}
__device__ __forceinline__ void st4(__half* p, float4 v) {
    __half2 h0 = __floats2half2_rn(v.x, v.y);
    __half2 h1 = __floats2half2_rn(v.z, v.w);
    uint2 u;
    u.x = *reinterpret_cast<unsigned*>(&h0);
    u.y = *reinterpret_cast<unsigned*>(&h1);
    *(uint2*)p = u;  // one 8B store
}

// ---------------------------------------------------------------------------
// Edge dtype detection: int64 little-endian with values < 2^31 has every odd
// 32-bit word == 0. Random int32 node ids make that astronomically unlikely.
__global__ void detect_kernel(const void* ei) {
    if (threadIdx.x == 0) {
        const int* w = (const int*)ei;
        int all0 = 1;
#pragma unroll 1
        for (int i = 1; i < 256; i += 2) all0 &= (w[i] == 0);
        g_is64 = all0;
    }
}

// In-degree histogram, reading edge_index[1] (targets) directly.
// g_cnt starts zero: zero-init at module load for call 1, re-zeroed by
// scanwrite_kernel (last reader) at the end of every call.
__global__ void hist_kernel(const void* ei) {
    int i = blockIdx.x * blockDim.x + threadIdx.x;
    if (i >= EE) return;
    int d;
    if (g_is64) {
        d = (int)((const long long*)ei)[EE + i];
    } else {
        d = ((const int*)ei)[EE + i];
    }
    atomicAdd(&g_cnt[d], 1);
}

// ---------------------------------------------------------------------------
// Hierarchical exclusive scan over g_cnt (3 tiny kernels, all-SM parallel).
__global__ void bsum_kernel() {
    __shared__ int sw[8];
    int i = blockIdx.x * SCAN_B + threadIdx.x;
    int v = (i < NN) ? g_cnt[i] : 0;
#pragma unroll
    for (int o = 16; o > 0; o >>= 1) v += __shfl_down_sync(~0u, v, o);
    int lane = threadIdx.x & 31, w = threadIdx.x >> 5;
    if (lane == 0) sw[w] = v;
    __syncthreads();
    if (threadIdx.x < 8) {
        int s = sw[threadIdx.x];
#pragma unroll
        for (int o = 4; o > 0; o >>= 1) s += __shfl_down_sync(0xff, s, o);
        if (threadIdx.x == 0) g_bsum[blockIdx.x] = s;
    }
}

__global__ void boff_kernel() {
    __shared__ int sm[256];
    int tid = threadIdx.x;
    int v = (tid < NBLK) ? g_bsum[tid] : 0;
    sm[tid] = v;
    __syncthreads();
    for (int d = 1; d < 256; d <<= 1) {
        int t = (tid >= d) ? sm[tid - d] : 0;
        __syncthreads();
        sm[tid] += t;
        __syncthreads();
    }
    if (tid < NBLK) g_boff[tid] = sm[tid] - v;  // exclusive
    if (tid == 255) g_rowptr[NN] = sm[255];
}

__global__ void scanwrite_kernel() {
    __shared__ int swarp[8];
    int tid = threadIdx.x;
    int i = blockIdx.x * SCAN_B + tid;
    int c = (i < NN) ? g_cnt[i] : 0;
    int v = c;
    int lane = tid & 31, w = tid >> 5;
#pragma unroll
    for (int o = 1; o < 32; o <<= 1) {
        int t = __shfl_up_sync(~0u, v, o);
        if (lane >= o) v += t;
    }
    if (lane == 31) swarp[w] = v;
    __syncthreads();
    if (tid < 8) {
        int s = swarp[tid];
#pragma unroll
        for (int o = 1; o < 8; o <<= 1) {
            int t = __shfl_up_sync(0xff, s, o);
            if (tid >= o) s += t;
        }
        swarp[tid] = s;
    }
    __syncthreads();
    int excl = v - c + (w > 0 ? swarp[w - 1] : 0) + g_boff[blockIdx.x];
    if (i < NN) {
        g_rowptr[i] = excl;
        g_cursor[i] = excl;
        g_dinv[i] = rsqrtf((float)c + 1.0f);
        g_cnt[i] = 0;  // self-zero for the next call (we are the last reader)
    }
}

// ---------------------------------------------------------------------------
// GEMM (FMA-pipe-bound at fp32 floor): [NN,128] x [128,128].
// W resident in smem. 8 warps/block, each warp 4 rows x 128 cols.
// out16 != 0 (and B1 == null): write O0 as fp16.
// B1 != null: B = [B0 | B1] (128x64 each), split fp32 outputs O0/O1.
// ei != null: thread-level fused CSR scatter before GEMM work (same
// blocks/smem as pure GEMM -> no occupancy penalty; atomic-bound scatter
// hides under the FMA-bound GEMM).
__global__ void __launch_bounds__(256, 2) gemm128_kernel(
    const float* __restrict__ X, const float* __restrict__ B0,
    const float* __restrict__ B1, const float* __restrict__ bias0,
    const float* __restrict__ bias1, void* __restrict__ O0v,
    float* __restrict__ O1, int do_relu, int out16, const void* ei) {
    extern __shared__ float sm[];
    float* Wsm = sm;              // 128*128 floats
    float* xs = sm + 128 * 128;   // 8 warps * 4 rows * 128 floats
    int tid = threadIdx.x, w = tid >> 5, lane = tid & 31;

    if (ei) {  // fused scatter: ~2 edges per thread
        int stride = gridDim.x * blockDim.x;
        if (g_is64) {
            const long long* p = (const long long*)ei;
            for (int i = blockIdx.x * blockDim.x + tid; i < EE; i += stride) {
                int s = (int)p[i];
                int d = (int)p[EE + i];
                int pos = atomicAdd(&g_cursor[d], 1);
                g_csr[pos] = s;
            }
        } else {
            const int* p = (const int*)ei;
            for (int i = blockIdx.x * blockDim.x + tid; i < EE; i += stride) {
                int s = p[i];
                int d = p[EE + i];
                int pos = atomicAdd(&g_cursor[d], 1);
                g_csr[pos] = s;
            }
        }
    }

    for (int idx = tid; idx < 128 * 128; idx += 256) {
        float v;
        if (B1) {
            int k = idx >> 7, n = idx & 127;
            v = (n < 64) ? B0[(k << 6) + n] : B1[(k << 6) + n - 64];
        } else {
            v = B0[idx];
        }
        Wsm[idx] = v;
    }
    __syncthreads();

    int row0 = (blockIdx.x * 8 + w) * 4;
    if (row0 >= NN) return;
    float* xw = xs + w * 4 * 128;

#pragma unroll
    for (int r = 0; r < 4; r++) {
        int row = row0 + r;
        float4 v = (row < NN) ? *(const float4*)(X + (size_t)row * 128 + lane * 4)
                              : make_float4(0.f, 0.f, 0.f, 0.f);
        *(float4*)(xw + r * 128 + lane * 4) = v;
    }
    __syncwarp();

    float4 a0 = make_float4(0.f, 0.f, 0.f, 0.f), a1 = a0, a2 = a0, a3 = a0;
#pragma unroll 16
    for (int k = 0; k < 128; k++) {
        float4 wv = *(float4*)(Wsm + k * 128 + lane * 4);
        float x0 = xw[0 * 128 + k];
        float x1 = xw[1 * 128 + k];
        float x2 = xw[2 * 128 + k];
        float x3 = xw[3 * 128 + k];
        a0.x += x0 * wv.x; a0.y += x0 * wv.y; a0.z += x0 * wv.z; a0.w += x0 * wv.w;
        a1.x += x1 * wv.x; a1.y += x1 * wv.y; a1.z += x1 * wv.z; a1.w += x1 * wv.w;
        a2.x += x2 * wv.x; a2.y += x2 * wv.y; a2.z += x2 * wv.z; a2.w += x2 * wv.w;
        a3.x += x3 * wv.x; a3.y += x3 * wv.y; a3.z += x3 * wv.z; a3.w += x3 * wv.w;
    }

    int col = lane * 4;
    float4 bi = make_float4(0.f, 0.f, 0.f, 0.f);
    if (bias0) {
        if (B1)
            bi = (col < 64) ? *(const float4*)(bias0 + col)
                            : *(const float4*)(bias1 + col - 64);
        else
            bi = *(const float4*)(bias0 + col);
    }
    float4 accs[4] = {a0, a1, a2, a3};
#pragma unroll
    for (int r = 0; r < 4; r++) {
        int row = row0 + r;
        if (row >= NN) break;
        float4 o = accs[r];
        o.x += bi.x; o.y += bi.y; o.z += bi.z; o.w += bi.w;
        if (do_relu) {
            o.x = fmaxf(o.x, 0.f); o.y = fmaxf(o.y, 0.f);
            o.z = fmaxf(o.z, 0.f); o.w = fmaxf(o.w, 0.f);
        }
        if (B1) {
            float* O0 = (float*)O0v;
            if (col < 64)
                *(float4*)(O0 + (size_t)row * 64 + col) = o;
            else
                *(float4*)(O1 + (size_t)row * 64 + col - 64) = o;
        } else if (out16) {
            st4((__half*)O0v + (size_t)row * 128 + col, o);
        } else {
            st4((float*)O0v + (size_t)row * 128 + col, o);
        }
    }
}

// ---------------------------------------------------------------------------
// Aggregation (R5-proven loop shape — ptxas unrolls the gather for MLP; no
// unroll pragmas / manual prefetch, R8 showed that regresses).
// OUT[c] = dinv[c]*(sum_{r in in(c)} dinv[r]*H[r]) + dinv[c]^2*H[c]
// TIN/TOUT: fp16 storage halves LTS gather traffic; compute stays fp32.
template <typename TIN, typename TOUT>
__global__ void agg_kernel(const TIN* __restrict__ H, TOUT* __restrict__ OUT,
                           const float* __restrict__ bias, int do_relu) {
    int gw = (blockIdx.x * blockDim.x + threadIdx.x) >> 5;
    if (gw >= NN) return;
    int lane = threadIdx.x & 31;
    int node = gw;
    int s = g_rowptr[node], e = g_rowptr[node + 1];
    float ax = 0.f, ay = 0.f, az = 0.f, aw = 0.f;
    for (int j = s; j < e; j++) {
        int src = g_csr[j];
        float wgt = g_dinv[src];
        float4 v = ld4(H + (size_t)src * 128 + lane * 4);
        ax += wgt * v.x; ay += wgt * v.y; az += wgt * v.z; aw += wgt * v.w;
    }
    float dc = g_dinv[node];
    float dc2 = dc * dc;
    float4 sv = ld4(H + (size_t)node * 128 + lane * 4);
    ax = dc * ax + dc2 * sv.x;
    ay = dc * ay + dc2 * sv.y;
    az = dc * az + dc2 * sv.z;
    aw = dc * aw + dc2 * sv.w;
    if (bias) {
        float4 bi = *(const float4*)(bias + lane * 4);
        ax += bi.x; ay += bi.y; az += bi.z; aw += bi.w;
    }
    if (do_relu) {
        ax = fmaxf(ax, 0.f); ay = fmaxf(ay, 0.f);
        az = fmaxf(az, 0.f); aw = fmaxf(aw, 0.f);
    }
    st4(OUT + (size_t)node * 128 + lane * 4, make_float4(ax, ay, az, aw));
}

// ---------------------------------------------------------------------------
extern "C" void kernel_launch(void* const* d_in, const int* in_sizes, int n_in,
                              void* d_out, int out_size) {
    const float* x = (const float*)d_in[0];
    const void* ei = d_in[1];
    const float* W1 = (const float*)d_in[2];
    const float* b1 = (const float*)d_in[3];
    const float* W2 = (const float*)d_in[4];
    const float* b2 = (const float*)d_in[5];
    const float* W3 = (const float*)d_in[6];
    const float* b3 = (const float*)d_in[7];
    float* out = (float*)d_out;

    float* pf32;
    __half* phh;
    __half* phid;
    cudaGetSymbolAddress((void**)&pf32, g_f32buf);
    cudaGetSymbolAddress((void**)&phh, g_hh);
    cudaGetSymbolAddress((void**)&phid, g_hid);

    const size_t smem = (128 * 128 + 8 * 4 * 128) * sizeof(float);  // 80 KB
    cudaFuncSetAttribute(gemm128_kernel,
                         cudaFuncAttributeMaxDynamicSharedMemorySize,
                         (int)smem);

    // CSR build prefix (scatter is fused into GEMM1; g_cnt self-zeroed by
    // scanwrite each call)
    detect_kernel<<<1, 32>>>(ei);
    hist_kernel<<<(EE + 255) / 256, 256>>>(ei);
    bsum_kernel<<<NBLK, SCAN_B>>>();
    boff_kernel<<<1, 256>>>();
    scanwrite_kernel<<<NBLK, SCAN_B>>>();

    int gblocks = (NN + 31) / 32;
    int ablocks = (NN * 32 + 255) / 256;

    // h = x @ W1 -> fp16, with CSR scatter fused in
    gemm128_kernel<<<gblocks, 256, smem>>>(x, W1, nullptr, nullptr, nullptr,
                                           phh, nullptr, 0, 1, ei);
    // hidden = relu(A h + b1) -> fp16 (gathers fp16: half the LTS traffic)
    agg_kernel<__half, __half><<<ablocks, 256>>>(phh, phid, b1, 1);
    // aggH = A hidden -> fp32 (shared by both heads)
    agg_kernel<__half, float><<<ablocks, 256>>>(phid, pf32, nullptr, 0);
    // x1 = relu(aggH @ W2 + b2), x2 = relu(aggH @ W3 + b3)
    gemm128_kernel<<<gblocks, 256, smem>>>(pf32, W2, W3, b2, b3, out,
                                           out + (size_t)NN * 64, 1, 0,
                                           nullptr);
}

// round 13
// speedup vs baseline: 1.8128x; 1.4396x over previous
#include <cuda_runtime.h>
#include <cuda_fp16.h>

#define NN 50000
#define EE 800000
#define SCAN_B 256
#define NBLK ((NN + SCAN_B - 1) / SCAN_B)  // 196
#define GB ((NN + 127) / 128)              // 391 gemm blocks

#define LDAB 136  // fp16 smem leading dim (68 words; 68 mod 32 = 4 -> conflict-free frags)
#define LDC 132   // fp32 epilogue smem leading dim (<=2-way)

// Scratch (no allocation allowed -> __device__ globals)
__device__ __half g_hh[NN * 128];      // h (then reused for aggH), fp16
__device__ __half g_hid[NN * 128];     // hidden, fp16
__device__ int g_csr[EE];
__device__ int g_cnt[NN];              // zero-init at load; self-zeroing per call
__device__ int g_rowptr[NN + 1];
__device__ int g_cursor[NN];
__device__ float g_dinv[NN];
__device__ int g_is64;
__device__ int g_bsum[NBLK];
__device__ int g_boff[NBLK];

// ---------------------------------------------------------------------------
__device__ __forceinline__ float4 ld4(const float* p) {
    return *(const float4*)p;
}
__device__ __forceinline__ float4 ld4(const __half* p) {
    uint2 u = *(const uint2*)p;
    __half2 h0 = *reinterpret_cast<__half2*>(&u.x);
    __half2 h1 = *reinterpret_cast<__half2*>(&u.y);
    float2 f0 = __half22float2(h0), f1 = __half22float2(h1);
    return make_float4(f0.x, f0.y, f1.x, f1.y);
}
__device__ __forceinline__ void st4(float* p, float4 v) { *(float4*)p = v; }
__device__ __forceinline__ void st4(__half* p, float4 v) {
    __half2 h0 = __floats2half2_rn(v.x, v.y);
    __half2 h1 = __floats2half2_rn(v.z, v.w);
    uint2 u;
    u.x = *reinterpret_cast<unsigned*>(&h0);
    u.y = *reinterpret_cast<unsigned*>(&h1);
    *(uint2*)p = u;
}

// m16n8k16 HMMA, fp16 inputs, fp32 accumulate (supported warp-MMA on sm_103a)
__device__ __forceinline__ void mma16816(float* c, const unsigned* a,
                                         const unsigned* b) {
    asm volatile(
        "mma.sync.aligned.m16n8k16.row.col.f32.f16.f16.f32 "
        "{%0,%1,%2,%3}, {%4,%5,%6,%7}, {%8,%9}, {%0,%1,%2,%3};"
        : "+f"(c[0]), "+f"(c[1]), "+f"(c[2]), "+f"(c[3])
        : "r"(a[0]), "r"(a[1]), "r"(a[2]), "r"(a[3]), "r"(b[0]), "r"(b[1]));
}

// ---------------------------------------------------------------------------
// Edge dtype detection: int64 little-endian with values < 2^31 has every odd
// 32-bit word == 0. Random int32 node ids make that astronomically unlikely.
__global__ void detect_kernel(const void* ei) {
    if (threadIdx.x == 0) {
        const int* w = (const int*)ei;
        int all0 = 1;
#pragma unroll 1
        for (int i = 1; i < 256; i += 2) all0 &= (w[i] == 0);
        g_is64 = all0;
    }
}

// In-degree histogram (g_cnt zeroed by scanwrite at end of each call).
__global__ void hist_kernel(const void* ei) {
    int i = blockIdx.x * blockDim.x + threadIdx.x;
    if (i >= EE) return;
    int d;
    if (g_is64) {
        d = (int)((const long long*)ei)[EE + i];
    } else {
        d = ((const int*)ei)[EE + i];
    }
    atomicAdd(&g_cnt[d], 1);
}

// ---------------------------------------------------------------------------
// Hierarchical exclusive scan over g_cnt (3 tiny kernels, all-SM parallel).
__global__ void bsum_kernel() {
    __shared__ int sw[8];
    int i = blockIdx.x * SCAN_B + threadIdx.x;
    int v = (i < NN) ? g_cnt[i] : 0;
#pragma unroll
    for (int o = 16; o > 0; o >>= 1) v += __shfl_down_sync(~0u, v, o);
    int lane = threadIdx.x & 31, w = threadIdx.x >> 5;
    if (lane == 0) sw[w] = v;
    __syncthreads();
    if (threadIdx.x < 8) {
        int s = sw[threadIdx.x];
#pragma unroll
        for (int o = 4; o > 0; o >>= 1) s += __shfl_down_sync(0xff, s, o);
        if (threadIdx.x == 0) g_bsum[blockIdx.x] = s;
    }
}

__global__ void boff_kernel() {
    __shared__ int sm[256];
    int tid = threadIdx.x;
    int v = (tid < NBLK) ? g_bsum[tid] : 0;
    sm[tid] = v;
    __syncthreads();
    for (int d = 1; d < 256; d <<= 1) {
        int t = (tid >= d) ? sm[tid - d] : 0;
        __syncthreads();
        sm[tid] += t;
        __syncthreads();
    }
    if (tid < NBLK) g_boff[tid] = sm[tid] - v;  // exclusive
    if (tid == 255) g_rowptr[NN] = sm[255];
}

__global__ void scanwrite_kernel() {
    __shared__ int swarp[8];
    int tid = threadIdx.x;
    int i = blockIdx.x * SCAN_B + tid;
    int c = (i < NN) ? g_cnt[i] : 0;
    int v = c;
    int lane = tid & 31, w = tid >> 5;
#pragma unroll
    for (int o = 1; o < 32; o <<= 1) {
        int t = __shfl_up_sync(~0u, v, o);
        if (lane >= o) v += t;
    }
    if (lane == 31) swarp[w] = v;
    __syncthreads();
    if (tid < 8) {
        int s = swarp[tid];
#pragma unroll
        for (int o = 1; o < 8; o <<= 1) {
            int t = __shfl_up_sync(0xff, s, o);
            if (tid >= o) s += t;
        }
        swarp[tid] = s;
    }
    __syncthreads();
    int excl = v - c + (w > 0 ? swarp[w - 1] : 0) + g_boff[blockIdx.x];
    if (i < NN) {
        g_rowptr[i] = excl;
        g_cursor[i] = excl;
        g_dinv[i] = rsqrtf((float)c + 1.0f);
        g_cnt[i] = 0;  // self-zero for the next call (we are the last reader)
    }
}

// ---------------------------------------------------------------------------
// Tensor-core GEMM via mma.sync m16n8k16 (fp16 in / fp32 accum):
// [NN,128] x [128,128]. Block = 128x128 tile, 8 warps (4m x 2n),
// warp = 32x64 = 2x8 HMMA tiles. A from row-major As[row][k]; B from
// TRANSPOSED BsT[n][k] so each b-reg k-pair is one LDS.32. Fragment loads
// follow the documented per-lane layout (groupID=lane>>2, tig=lane&3).
// Epilogue via smem Cs (reused space): bias / relu / split / fp16-out.
// ei != null: thread-level fused CSR scatter before GEMM work.
__global__ void __launch_bounds__(256, 1) gemm_tc_kernel(
    const void* __restrict__ Xv, const float* __restrict__ B0,
    const float* __restrict__ B1, const float* __restrict__ bias0,
    const float* __restrict__ bias1, void* __restrict__ O0v,
    float* __restrict__ O1, int do_relu, int in16, int out16,
    const void* ei) {
    extern __shared__ char smem[];
    __half* As = (__half*)smem;           // 128 x LDAB halves
    __half* BsT = As + 128 * LDAB;        // 128 x LDAB halves (W transposed)
    float* Cs = (float*)smem;             // 128 x LDC floats (reuse)
    int tid = threadIdx.x;

    if (ei) {  // fused scatter: ~8 edges per thread
        int stride = gridDim.x * blockDim.x;
        if (g_is64) {
            const long long* p = (const long long*)ei;
            for (int i = blockIdx.x * blockDim.x + tid; i < EE; i += stride) {
                int s = (int)p[i];
                int d = (int)p[EE + i];
                int pos = atomicAdd(&g_cursor[d], 1);
                g_csr[pos] = s;
            }
        } else {
            const int* p = (const int*)ei;
            for (int i = blockIdx.x * blockDim.x + tid; i < EE; i += stride) {
                int s = p[i];
                int d = p[EE + i];
                int pos = atomicAdd(&g_cursor[d], 1);
                g_csr[pos] = s;
            }
        }
    }

    int row0 = blockIdx.x * 128;

    // Fill As (X tile, fp16), 4 elements per idx step
    for (int idx = tid; idx < 128 * 32; idx += 256) {
        int r = idx >> 5, c4 = idx & 31;
        int grow = row0 + r;
        float4 v;
        if (grow >= NN) {
            v = make_float4(0.f, 0.f, 0.f, 0.f);
        } else if (in16) {
            v = ld4((const __half*)Xv + (size_t)grow * 128 + c4 * 4);
        } else {
            v = ld4((const float*)Xv + (size_t)grow * 128 + c4 * 4);
        }
        st4(As + r * LDAB + c4 * 4, v);
    }
    // Fill BsT (W transposed, fp16): BsT[n][k] = W[k][n]
    for (int idx = tid; idx < 128 * 32; idx += 256) {
        int k = idx >> 5, c4 = idx & 31;
        int n = c4 * 4;
        float4 v;
        if (B1) {
            v = (n < 64) ? ld4(B0 + k * 64 + n) : ld4(B1 + k * 64 + n - 64);
        } else {
            v = ld4(B0 + k * 128 + n);
        }
        BsT[(n + 0) * LDAB + k] = __float2half_rn(v.x);
        BsT[(n + 1) * LDAB + k] = __float2half_rn(v.y);
        BsT[(n + 2) * LDAB + k] = __float2half_rn(v.z);
        BsT[(n + 3) * LDAB + k] = __float2half_rn(v.w);
    }
    __syncthreads();

    int warp = tid >> 5, lane = tid & 31;
    int wm = warp >> 1, wn = warp & 1;   // 4 x 2 warp grid
    int g = lane >> 2, tig = lane & 3;   // mma fragment coords

    float c[2][8][4];
#pragma unroll
    for (int mi = 0; mi < 2; mi++)
#pragma unroll
        for (int ni = 0; ni < 8; ni++)
#pragma unroll
            for (int q = 0; q < 4; q++) c[mi][ni][q] = 0.f;

    const unsigned* As32 = (const unsigned*)As;
    const unsigned* Bs32 = (const unsigned*)BsT;
    const int LW = LDAB >> 1;  // 68 words per row

#pragma unroll
    for (int k0 = 0; k0 < 128; k0 += 16) {
        int kw = (k0 >> 1) + tig;  // word offset of this lane's k-pair
        unsigned a[2][4], b[8][2];
#pragma unroll
        for (int mi = 0; mi < 2; mi++) {
            int r = wm * 32 + mi * 16 + g;
            int base = r * LW + kw;
            a[mi][0] = As32[base];
            a[mi][1] = As32[base + 8 * LW];
            a[mi][2] = As32[base + 4];
            a[mi][3] = As32[base + 8 * LW + 4];
        }
#pragma unroll
        for (int ni = 0; ni < 8; ni++) {
            int n = wn * 64 + ni * 8 + g;
            int base = n * LW + kw;
            b[ni][0] = Bs32[base];
            b[ni][1] = Bs32[base + 4];
        }
#pragma unroll
        for (int mi = 0; mi < 2; mi++)
#pragma unroll
            for (int ni = 0; ni < 8; ni++)
                mma16816(c[mi][ni], a[mi], b[ni]);
    }

    __syncthreads();  // all warps done reading As/BsT before Cs overwrite

#pragma unroll
    for (int mi = 0; mi < 2; mi++) {
        int r = wm * 32 + mi * 16 + g;
#pragma unroll
        for (int ni = 0; ni < 8; ni++) {
            int col = wn * 64 + ni * 8 + tig * 2;
            *(float2*)(Cs + r * LDC + col) =
                make_float2(c[mi][ni][0], c[mi][ni][1]);
            *(float2*)(Cs + (r + 8) * LDC + col) =
                make_float2(c[mi][ni][2], c[mi][ni][3]);
        }
    }
    __syncthreads();

    // Epilogue: bias / relu / dtype / split
    for (int idx = tid; idx < 128 * 32; idx += 256) {
        int r = idx >> 5, c4 = idx & 31;
        int grow = row0 + r;
        if (grow >= NN) continue;
        int col = c4 * 4;
        float4 o = *(float4*)(Cs + r * LDC + col);
        if (bias0) {
            float4 bi;
            if (B1)
                bi = (col < 64) ? *(const float4*)(bias0 + col)
                                : *(const float4*)(bias1 + col - 64);
            else
                bi = *(const float4*)(bias0 + col);
            o.x += bi.x; o.y += bi.y; o.z += bi.z; o.w += bi.w;
        }
        if (do_relu) {
            o.x = fmaxf(o.x, 0.f); o.y = fmaxf(o.y, 0.f);
            o.z = fmaxf(o.z, 0.f); o.w = fmaxf(o.w, 0.f);
        }
        if (B1) {
            float* O0 = (float*)O0v;
            if (col < 64)
                *(float4*)(O0 + (size_t)grow * 64 + col) = o;
            else
                *(float4*)(O1 + (size_t)grow * 64 + col - 64) = o;
        } else if (out16) {
            st4((__half*)O0v + (size_t)grow * 128 + col, o);
        } else {
            st4((float*)O0v + (size_t)grow * 128 + col, o);
        }
    }
}

// ---------------------------------------------------------------------------
// Aggregation (R5-proven loop shape — ptxas unrolls the gather for MLP).
// OUT[c] = dinv[c]*(sum_{r in in(c)} dinv[r]*H[r]) + dinv[c]^2*H[c]
template <typename TIN, typename TOUT>
__global__ void agg_kernel(const TIN* __restrict__ H, TOUT* __restrict__ OUT,
                           const float* __restrict__ bias, int do_relu) {
    int gw = (blockIdx.x * blockDim.x + threadIdx.x) >> 5;
    if (gw >= NN) return;
    int lane = threadIdx.x & 31;
    int node = gw;
    int s = g_rowptr[node], e = g_rowptr[node + 1];
    float ax = 0.f, ay = 0.f, az = 0.f, aw = 0.f;
    for (int j = s; j < e; j++) {
        int src = g_csr[j];
        float wgt = g_dinv[src];
        float4 v = ld4(H + (size_t)src * 128 + lane * 4);
        ax += wgt * v.x; ay += wgt * v.y; az += wgt * v.z; aw += wgt * v.w;
    }
    float dc = g_dinv[node];
    float dc2 = dc * dc;
    float4 sv = ld4(H + (size_t)node * 128 + lane * 4);
    ax = dc * ax + dc2 * sv.x;
    ay = dc * ay + dc2 * sv.y;
    az = dc * az + dc2 * sv.z;
    aw = dc * aw + dc2 * sv.w;
    if (bias) {
        float4 bi = *(const float4*)(bias + lane * 4);
        ax += bi.x; ay += bi.y; az += bi.z; aw += bi.w;
    }
    if (do_relu) {
        ax = fmaxf(ax, 0.f); ay = fmaxf(ay, 0.f);
        az = fmaxf(az, 0.f); aw = fmaxf(aw, 0.f);
    }
    st4(OUT + (size_t)node * 128 + lane * 4, make_float4(ax, ay, az, aw));
}

// ---------------------------------------------------------------------------
extern "C" void kernel_launch(void* const* d_in, const int* in_sizes, int n_in,
                              void* d_out, int out_size) {
    const float* x = (const float*)d_in[0];
    const void* ei = d_in[1];
    const float* W1 = (const float*)d_in[2];
    const float* b1 = (const float*)d_in[3];
    const float* W2 = (const float*)d_in[4];
    const float* b2 = (const float*)d_in[5];
    const float* W3 = (const float*)d_in[6];
    const float* b3 = (const float*)d_in[7];
    float* out = (float*)d_out;

    __half* phh;
    __half* phid;
    cudaGetSymbolAddress((void**)&phh, g_hh);
    cudaGetSymbolAddress((void**)&phid, g_hid);

    const size_t smem = 2 * 128 * LDAB * sizeof(__half);  // 69632 B
    cudaFuncSetAttribute(gemm_tc_kernel,
                         cudaFuncAttributeMaxDynamicSharedMemorySize,
                         (int)smem);

    // CSR build prefix (scatter fused into GEMM1)
    detect_kernel<<<1, 32>>>(ei);
    hist_kernel<<<(EE + 255) / 256, 256>>>(ei);
    bsum_kernel<<<NBLK, SCAN_B>>>();
    boff_kernel<<<1, 256>>>();
    scanwrite_kernel<<<NBLK, SCAN_B>>>();

    int ablocks = (NN * 32 + 255) / 256;

    // h = x @ W1 -> fp16 (tensor cores), CSR scatter fused
    gemm_tc_kernel<<<GB, 256, smem>>>(x, W1, nullptr, nullptr, nullptr,
                                      phh, nullptr, 0, 0, 1, ei);
    // hidden = relu(A h + b1) -> fp16
    agg_kernel<__half, __half><<<ablocks, 256>>>(phh, phid, b1, 1);
    // aggH = A hidden -> fp16 (reuses g_hh; h is dead after agg1)
    agg_kernel<__half, __half><<<ablocks, 256>>>(phid, phh, nullptr, 0);
    // x1 = relu(aggH @ W2 + b2), x2 = relu(aggH @ W3 + b3)  (tensor cores)
    gemm_tc_kernel<<<GB, 256, smem>>>(phh, W2, W3, b2, b3, out,
                                      out + (size_t)NN * 64, 1, 1, 0,
                                      nullptr);
}